// round 10
// baseline (speedup 1.0000x reference)
#include <cuda_runtime.h>
#include <cuda_bf16.h>

#define B_     8
#define N_     2048
#define FIN    128
#define FOUT   64
#define ALPHA  0.2f
#define JSPLIT 4

// Scratch (device globals — no allocation allowed)
__device__ float g_Wh[B_ * N_ * FOUT];            // 4 MB
__device__ float g_f[B_ * N_];
__device__ float g_g[B_ * N_];
__device__ float g_pacc[JSPLIT][B_ * N_ * FOUT];  // 16 MB partial accumulators
__device__ float g_psum[JSPLIT][B_ * N_];         // partial rowsums

// ---------------------------------------------------------------------------
// packed fp32x2 helpers (sm_100+ PTX; ptxas never emits FFMA2 from C++)
// ---------------------------------------------------------------------------
__device__ __forceinline__ unsigned long long fma2(unsigned long long a,
                                                   unsigned long long b,
                                                   unsigned long long c) {
    unsigned long long d;
    asm("fma.rn.f32x2 %0, %1, %2, %3;" : "=l"(d) : "l"(a), "l"(b), "l"(c));
    return d;
}
__device__ __forceinline__ unsigned long long pack2(float p) {
    unsigned long long d;
    asm("mov.b64 %0, {%1, %1};" : "=l"(d) : "r"(__float_as_uint(p)));
    return d;
}
__device__ __forceinline__ unsigned smem_u32(const void* p) {
    return (unsigned)__cvta_generic_to_shared(p);
}
#define CP16(dst, src) \
    asm volatile("cp.async.cg.shared.global [%0], [%1], 16;" :: "r"(dst), "l"(src))

// ---------------------------------------------------------------------------
// Kernel 1: Wh = h @ W ; f = Wh @ a1 ; g = Wh @ a2
// 64x64 tile, 256 threads, 4 rows x 4 cols per thread.
// W kept natural [k][c] (float4 over c); h padded stride 132 (conflict-free).
// Per k4-chunk: 4 W-loads + 4 h-loads per 64 FMA  (2.5x less LDS than before).
// ---------------------------------------------------------------------------
__global__ void __launch_bounds__(256) k_wh(const float* __restrict__ h,
                                            const float* __restrict__ W,
                                            const float* __restrict__ a) {
    __shared__ __align__(16) float W_s[FIN][FOUT];   // 32 KB, natural layout
    __shared__ __align__(16) float h_s[64][132];     // 33.8 KB, padded

    int row0 = blockIdx.x * 64;
    int tid  = threadIdx.x;
    int fc4  = (tid & 15) * 4;        // 4 output cols
    int rg   = tid >> 4;              // 0..15 -> rows rg*4 .. rg*4+3

    // load W (flat float4 copy, coalesced)
    #pragma unroll
    for (int l = 0; l < 8; l++) {
        int idx = tid + l * 256;          // 0..2047 float4
        *(float4*)&((float*)W_s)[idx * 4] = *(const float4*)&W[idx * 4];
    }
    // load 64 rows of h (padded rows)
    #pragma unroll
    for (int l = 0; l < 8; l++) {
        int idx = tid + l * 256;          // 0..2047 float4
        int r = idx >> 5, q = idx & 31;
        *(float4*)&h_s[r][q * 4] =
            *(const float4*)&h[(size_t)(row0 + r) * FIN + q * 4];
    }
    __syncthreads();

    float acc[4][4];
    #pragma unroll
    for (int r = 0; r < 4; r++)
        #pragma unroll
        for (int c = 0; c < 4; c++) acc[r][c] = 0.f;

    #pragma unroll 2
    for (int k4 = 0; k4 < FIN; k4 += 4) {
        float4 w0 = *(const float4*)&W_s[k4 + 0][fc4];
        float4 w1 = *(const float4*)&W_s[k4 + 1][fc4];
        float4 w2 = *(const float4*)&W_s[k4 + 2][fc4];
        float4 w3 = *(const float4*)&W_s[k4 + 3][fc4];
        #pragma unroll
        for (int r = 0; r < 4; r++) {
            float4 hv = *(const float4*)&h_s[rg * 4 + r][k4];
            const float* wp0 = (const float*)&w0;
            const float* wp1 = (const float*)&w1;
            const float* wp2 = (const float*)&w2;
            const float* wp3 = (const float*)&w3;
            #pragma unroll
            for (int c = 0; c < 4; c++) {
                float t = acc[r][c];
                t = fmaf(hv.x, wp0[c], t);
                t = fmaf(hv.y, wp1[c], t);
                t = fmaf(hv.z, wp2[c], t);
                t = fmaf(hv.w, wp3[c], t);
                acc[r][c] = t;
            }
        }
    }

    // store Wh + reduce f/g across the 16 col-threads of each row group
    float a1[4], a2[4];
    #pragma unroll
    for (int c = 0; c < 4; c++) { a1[c] = a[fc4 + c]; a2[c] = a[FOUT + fc4 + c]; }

    #pragma unroll
    for (int r = 0; r < 4; r++) {
        int row = row0 + rg * 4 + r;
        *(float4*)&g_Wh[(size_t)row * FOUT + fc4] = *(float4*)&acc[r][0];
        float pf = acc[r][0] * a1[0] + acc[r][1] * a1[1]
                 + acc[r][2] * a1[2] + acc[r][3] * a1[3];
        float pg = acc[r][0] * a2[0] + acc[r][1] * a2[1]
                 + acc[r][2] * a2[2] + acc[r][3] * a2[3];
        #pragma unroll
        for (int off = 1; off < 16; off <<= 1) {
            pf += __shfl_xor_sync(0xffffffffu, pf, off);
            pg += __shfl_xor_sync(0xffffffffu, pg, off);
        }
        if ((tid & 15) == 0) {
            g_f[row] = pf;
            g_g[row] = pg;
        }
    }
}

// ---------------------------------------------------------------------------
// Kernel 2: fused masked-softmax attention + att@Wh, j-split into JSPLIT
// blocks; writes UNNORMALIZED partial acc + partial rowsums.
// 128 threads, TI=128 rows, TJ=64 j-tile, 8 tiles/CTA.
//  score mapping: rows (tid>>2)+32m (m=0..3), cols (tid&3)*16 + 4k (k=0..3)
//                 -> adj LDG.128 touches 8 lines/instr (4 consec lanes per row)
//  accum mapping: cg=tid&7 (8 cols), rw=tid>>3 -> rows {rw+16m, m=0..7}
//                 8x8 per-thread tile -> 1.0 B smem/FMA (crossbar floor)
// Wh_s: 16B-chunk XOR swizzle -> conflict-free w LDS.128; p read as LDS.32.
// ---------------------------------------------------------------------------
#define TI 128
#define TJ 64
#define TH 128
#define STR 68

__global__ void __launch_bounds__(TH, 4) k_attn(const float* __restrict__ adj) {
    __shared__ __align__(16) float Wh_s[TJ][STR];   // 17.4 KB
    __shared__ __align__(16) float p_s[TI][STR];    // 34.8 KB
    __shared__ float f_s[TI];
    __shared__ float rowsum[TI];

    int i0    = blockIdx.x * TI;
    int js    = blockIdx.y;
    int b     = blockIdx.z;
    int jbase = js * (N_ / JSPLIT);
    int tid   = threadIdx.x;

    int s_r = tid >> 2;                // score base row (0..31)
    int s_c = (tid & 3) * 16;          // score col base
    int cg  = tid & 7;                 // accum col group (8 cols)
    int rw  = tid >> 3;                // accum base row (0..15)

    int oA = ((2 * cg)     ^ (((2 * cg)     >> 3) & 1)) * 4;
    int oB = ((2 * cg + 1) ^ (((2 * cg + 1) >> 3) & 1)) * 4;

    const float* Wh_b = g_Wh + (size_t)b * N_ * FOUT;
    const float* gg   = g_g + b * N_;

    f_s[tid]    = g_f[b * N_ + i0 + tid];
    rowsum[tid] = 0.f;
    __syncthreads();

    float fi[4];
    #pragma unroll
    for (int m = 0; m < 4; m++) fi[m] = f_s[s_r + 32 * m];

    unsigned long long acc[8][4];
    #pragma unroll
    for (int m = 0; m < 8; m++)
        #pragma unroll
        for (int c = 0; c < 4; c++) acc[m][c] = 0ull;

    for (int jt = 0; jt < (N_ / JSPLIT) / TJ; jt++) {
        int j0 = jbase + jt * TJ;
        if (jt) __syncthreads();       // prev accumulate done with Wh_s / p_s

        // ---- async-copy Wh tile gmem->shared (swizzled), overlaps score ----
        #pragma unroll
        for (int l = 0; l < 8; l++) {
            int idx = tid + TH * l;            // 0..1023 16B chunks
            int row = idx >> 4, q = idx & 15;
            int qs = q ^ ((q >> 3) & 1);
            CP16(smem_u32(&Wh_s[row][qs * 4]),
                 &Wh_b[(size_t)(j0 + row) * FOUT + q * 4]);
        }

        // ---- scores: p = adj>0 ? exp(lrelu(f_i + g_j)) : 0 ----
        #pragma unroll
        for (int m = 0; m < 4; m++) {
            int r = s_r + 32 * m;
            const float* arow = adj + (size_t)(i0 + r) * N_ + j0;
            float part = 0.f;
            #pragma unroll
            for (int k = 0; k < 4; k++) {
                int c = s_c + 4 * k;
                float4 ad = *(const float4*)&arow[c];
                float4 gv = *(const float4*)&gg[j0 + c];
                float4 P;
                float v;
                v = fi[m] + gv.x; v = fmaxf(v, ALPHA * v); P.x = (ad.x > 0.f) ? __expf(v) : 0.f;
                v = fi[m] + gv.y; v = fmaxf(v, ALPHA * v); P.y = (ad.y > 0.f) ? __expf(v) : 0.f;
                v = fi[m] + gv.z; v = fmaxf(v, ALPHA * v); P.z = (ad.z > 0.f) ? __expf(v) : 0.f;
                v = fi[m] + gv.w; v = fmaxf(v, ALPHA * v); P.w = (ad.w > 0.f) ? __expf(v) : 0.f;
                *(float4*)&p_s[r][c] = P;
                part += (P.x + P.y) + (P.z + P.w);
            }
            part += __shfl_xor_sync(0xffffffffu, part, 1);
            part += __shfl_xor_sync(0xffffffffu, part, 2);
            if (!(tid & 3)) rowsum[r] += part;
        }

        asm volatile("cp.async.wait_all;" ::: "memory");
        __syncthreads();

        // ---- accumulate: acc[m][*] += p[rw+16m][j] * Wh[j][cols] ----
        #pragma unroll 2
        for (int jc = 0; jc < TJ; jc += 4) {
            #pragma unroll
            for (int jj = 0; jj < 4; jj++) {
                ulonglong2 wA = *(const ulonglong2*)&Wh_s[jc + jj][oA];
                ulonglong2 wB = *(const ulonglong2*)&Wh_s[jc + jj][oB];
                #pragma unroll
                for (int m = 0; m < 8; m++) {
                    unsigned long long pd = pack2(p_s[rw + 16 * m][jc + jj]);
                    acc[m][0] = fma2(pd, wA.x, acc[m][0]);
                    acc[m][1] = fma2(pd, wA.y, acc[m][1]);
                    acc[m][2] = fma2(pd, wB.x, acc[m][2]);
                    acc[m][3] = fma2(pd, wB.y, acc[m][3]);
                }
            }
        }
    }
    __syncthreads();   // all rowsum contributions landed

    float* pa = g_pacc[js] + ((size_t)b * N_ + i0) * FOUT;
    #pragma unroll
    for (int m = 0; m < 8; m++) {
        int row = rw + 16 * m;
        float2 v0 = *(float2*)&acc[m][0];
        float2 v1 = *(float2*)&acc[m][1];
        float2 v2 = *(float2*)&acc[m][2];
        float2 v3 = *(float2*)&acc[m][3];
        float4 oa = make_float4(v0.x, v0.y, v1.x, v1.y);
        float4 ob = make_float4(v2.x, v2.y, v3.x, v3.y);
        *(float4*)&pa[(size_t)row * FOUT + 8 * cg]     = oa;
        *(float4*)&pa[(size_t)row * FOUT + 8 * cg + 4] = ob;
    }
    g_psum[js][b * N_ + i0 + tid] = rowsum[tid];
}

// ---------------------------------------------------------------------------
// Kernel 3: combine partials: out = (sum_js pacc) / (sum_js psum)
// ---------------------------------------------------------------------------
__global__ void __launch_bounds__(256) k_comb(float* __restrict__ out) {
    int idx = blockIdx.x * 256 + threadIdx.x;      // float4 index
    int row = idx >> 4;                            // 16 float4 per row
    float4 s = *(const float4*)&g_pacc[0][(size_t)idx * 4];
    float den = g_psum[0][row];
    #pragma unroll
    for (int js = 1; js < JSPLIT; js++) {
        float4 c = *(const float4*)&g_pacc[js][(size_t)idx * 4];
        s.x += c.x; s.y += c.y; s.z += c.z; s.w += c.w;
        den += g_psum[js][row];
    }
    float inv = 1.0f / den;
    float4 o = make_float4(s.x * inv, s.y * inv, s.z * inv, s.w * inv);
    *(float4*)&out[(size_t)idx * 4] = o;
}

// ---------------------------------------------------------------------------
extern "C" void kernel_launch(void* const* d_in, const int* in_sizes, int n_in,
                              void* d_out, int out_size) {
    const float* h   = (const float*)d_in[0];
    const float* adj = (const float*)d_in[1];
    const float* W   = (const float*)d_in[2];
    const float* a   = (const float*)d_in[3];
    float* out = (float*)d_out;

    k_wh<<<(B_ * N_) / 64, 256>>>(h, W, a);

    dim3 grid(N_ / TI, JSPLIT, B_);
    k_attn<<<grid, TH>>>(adj);

    k_comb<<<(B_ * N_ * FOUT / 4) / 256, 256>>>(out);
}

// round 11
// speedup vs baseline: 1.1627x; 1.1627x over previous
#include <cuda_runtime.h>
#include <cuda_bf16.h>

#define B_     8
#define N_     2048
#define FIN    128
#define FOUT   64
#define ALPHA  0.2f
#define JSPLIT 4

// Scratch (device globals — no allocation allowed)
__device__ float g_Wh[B_ * N_ * FOUT];            // 4 MB
__device__ float g_f[B_ * N_];
__device__ float g_g[B_ * N_];
__device__ float g_pacc[JSPLIT][B_ * N_ * FOUT];  // 16 MB partial accumulators
__device__ float g_psum[JSPLIT][B_ * N_];         // partial rowsums

// ---------------------------------------------------------------------------
// packed fp32x2 helpers (sm_100+ PTX; ptxas never emits FFMA2 from C++)
// ---------------------------------------------------------------------------
__device__ __forceinline__ unsigned long long fma2(unsigned long long a,
                                                   unsigned long long b,
                                                   unsigned long long c) {
    unsigned long long d;
    asm("fma.rn.f32x2 %0, %1, %2, %3;" : "=l"(d) : "l"(a), "l"(b), "l"(c));
    return d;
}
__device__ __forceinline__ unsigned long long pack2(float p) {
    unsigned long long d;
    asm("mov.b64 %0, {%1, %1};" : "=l"(d) : "r"(__float_as_uint(p)));
    return d;
}
__device__ __forceinline__ unsigned smem_u32(const void* p) {
    return (unsigned)__cvta_generic_to_shared(p);
}
#define CP16(dst, src) \
    asm volatile("cp.async.cg.shared.global [%0], [%1], 16;" :: "r"(dst), "l"(src))

// ---------------------------------------------------------------------------
// Kernel 1: Wh = h @ W ; f = Wh @ a1 ; g = Wh @ a2
// 64x64 tile, 256 threads, 4 rows x 4 cols per thread (round-10 version,
// measured 14.4us). W natural [k][c] (float4 over c); h padded stride 132.
// ---------------------------------------------------------------------------
__global__ void __launch_bounds__(256) k_wh(const float* __restrict__ h,
                                            const float* __restrict__ W,
                                            const float* __restrict__ a) {
    __shared__ __align__(16) float W_s[FIN][FOUT];   // 32 KB, natural layout
    __shared__ __align__(16) float h_s[64][132];     // 33.8 KB, padded

    int row0 = blockIdx.x * 64;
    int tid  = threadIdx.x;
    int fc4  = (tid & 15) * 4;        // 4 output cols
    int rg   = tid >> 4;              // 0..15 -> rows rg*4 .. rg*4+3

    // load W (flat float4 copy, coalesced)
    #pragma unroll
    for (int l = 0; l < 8; l++) {
        int idx = tid + l * 256;          // 0..2047 float4
        *(float4*)&((float*)W_s)[idx * 4] = *(const float4*)&W[idx * 4];
    }
    // load 64 rows of h (padded rows)
    #pragma unroll
    for (int l = 0; l < 8; l++) {
        int idx = tid + l * 256;          // 0..2047 float4
        int r = idx >> 5, q = idx & 31;
        *(float4*)&h_s[r][q * 4] =
            *(const float4*)&h[(size_t)(row0 + r) * FIN + q * 4];
    }
    __syncthreads();

    float acc[4][4];
    #pragma unroll
    for (int r = 0; r < 4; r++)
        #pragma unroll
        for (int c = 0; c < 4; c++) acc[r][c] = 0.f;

    #pragma unroll 2
    for (int k4 = 0; k4 < FIN; k4 += 4) {
        float4 w0 = *(const float4*)&W_s[k4 + 0][fc4];
        float4 w1 = *(const float4*)&W_s[k4 + 1][fc4];
        float4 w2 = *(const float4*)&W_s[k4 + 2][fc4];
        float4 w3 = *(const float4*)&W_s[k4 + 3][fc4];
        #pragma unroll
        for (int r = 0; r < 4; r++) {
            float4 hv = *(const float4*)&h_s[rg * 4 + r][k4];
            const float* wp0 = (const float*)&w0;
            const float* wp1 = (const float*)&w1;
            const float* wp2 = (const float*)&w2;
            const float* wp3 = (const float*)&w3;
            #pragma unroll
            for (int c = 0; c < 4; c++) {
                float t = acc[r][c];
                t = fmaf(hv.x, wp0[c], t);
                t = fmaf(hv.y, wp1[c], t);
                t = fmaf(hv.z, wp2[c], t);
                t = fmaf(hv.w, wp3[c], t);
                acc[r][c] = t;
            }
        }
    }

    // store Wh + reduce f/g across the 16 col-threads of each row group
    float a1[4], a2[4];
    #pragma unroll
    for (int c = 0; c < 4; c++) { a1[c] = a[fc4 + c]; a2[c] = a[FOUT + fc4 + c]; }

    #pragma unroll
    for (int r = 0; r < 4; r++) {
        int row = row0 + rg * 4 + r;
        *(float4*)&g_Wh[(size_t)row * FOUT + fc4] = *(float4*)&acc[r][0];
        float pf = acc[r][0] * a1[0] + acc[r][1] * a1[1]
                 + acc[r][2] * a1[2] + acc[r][3] * a1[3];
        float pg = acc[r][0] * a2[0] + acc[r][1] * a2[1]
                 + acc[r][2] * a2[2] + acc[r][3] * a2[3];
        #pragma unroll
        for (int off = 1; off < 16; off <<= 1) {
            pf += __shfl_xor_sync(0xffffffffu, pf, off);
            pg += __shfl_xor_sync(0xffffffffu, pg, off);
        }
        if ((tid & 15) == 0) {
            g_f[row] = pf;
            g_g[row] = pg;
        }
    }
}

// ---------------------------------------------------------------------------
// Kernel 2 (round-7 version, best measured): fused masked-softmax attention +
// att@Wh, j-split into JSPLIT blocks; writes UNNORMALIZED partials.
// 128 threads, TI=64, TJ=64, 8 tiles/CTA.
//  score mapping: sr = tid>>1 (row), cols (tid&1)*4 + 8k, k=0..7
//  accum mapping: cg = tid&7 (8 cols), rg = tid>>3 -> rows {rg,+16,+32,+48}
// Wh_s: 16B-chunk XOR swizzle -> 1 wf per w-LDS.128; p_s stride 68 bank-clean.
// ---------------------------------------------------------------------------
#define TI 64
#define TJ 64
#define TH 128
#define STR 68

__global__ void __launch_bounds__(TH, 5) k_attn(const float* __restrict__ adj) {
    __shared__ __align__(16) float Wh_s[TJ][STR];   // 17.4 KB
    __shared__ __align__(16) float p_s[TI][STR];    // 17.4 KB
    __shared__ float f_s[TI];
    __shared__ float rowsum[TI];

    int i0    = blockIdx.x * TI;
    int js    = blockIdx.y;
    int b     = blockIdx.z;
    int jbase = js * (N_ / JSPLIT);
    int tid   = threadIdx.x;

    int sr = tid >> 1;                 // score row
    int sq = (tid & 1) * 4;            // score col phase
    int cg = tid & 7;                  // accum col group (8 cols)
    int rg = tid >> 3;                 // accum rows {rg, rg+16, rg+32, rg+48}

    int oA = ((2 * cg)     ^ (((2 * cg)     >> 3) & 1)) * 4;
    int oB = ((2 * cg + 1) ^ (((2 * cg + 1) >> 3) & 1)) * 4;

    const float* Wh_b  = g_Wh + (size_t)b * N_ * FOUT;
    const float* gg    = g_g + b * N_;
    const float* adj_r = adj + (size_t)(i0 + sr) * N_ + jbase;

    if (tid < TI) {
        f_s[tid]    = g_f[b * N_ + i0 + tid];
        rowsum[tid] = 0.f;
    }
    __syncthreads();
    const float fi = f_s[sr];

    unsigned long long acc[4][4];
    #pragma unroll
    for (int r = 0; r < 4; r++)
        #pragma unroll
        for (int c = 0; c < 4; c++) acc[r][c] = 0ull;

    for (int jt = 0; jt < (N_ / JSPLIT) / TJ; jt++) {
        int j0 = jbase + jt * TJ;
        if (jt) __syncthreads();       // prev accumulate done with Wh_s / p_s

        // ---- async-copy Wh tile gmem->shared (swizzled), overlaps score ----
        #pragma unroll
        for (int l = 0; l < 8; l++) {
            int idx = tid + TH * l;            // 0..1023 16B chunks
            int row = idx >> 4, q = idx & 15;
            int qs = q ^ ((q >> 3) & 1);
            CP16(smem_u32(&Wh_s[row][qs * 4]),
                 &Wh_b[(size_t)(j0 + row) * FOUT + q * 4]);
        }

        // ---- scores: p = adj>0 ? exp(lrelu(f_i + g_j)) : 0 ----
        float part = 0.f;
        #pragma unroll
        for (int k = 0; k < 8; k++) {
            int c = sq + 8 * k;
            float4 ad = *(const float4*)&adj_r[jt * TJ + c];
            float4 gv = *(const float4*)&gg[j0 + c];
            float4 P;
            float v;
            v = fi + gv.x; v = fmaxf(v, ALPHA * v); P.x = (ad.x > 0.f) ? __expf(v) : 0.f;
            v = fi + gv.y; v = fmaxf(v, ALPHA * v); P.y = (ad.y > 0.f) ? __expf(v) : 0.f;
            v = fi + gv.z; v = fmaxf(v, ALPHA * v); P.z = (ad.z > 0.f) ? __expf(v) : 0.f;
            v = fi + gv.w; v = fmaxf(v, ALPHA * v); P.w = (ad.w > 0.f) ? __expf(v) : 0.f;
            *(float4*)&p_s[sr][c] = P;
            part += (P.x + P.y) + (P.z + P.w);
        }
        part += __shfl_xor_sync(0xffffffffu, part, 1);
        if (!(tid & 1)) rowsum[sr] += part;

        asm volatile("cp.async.wait_all;" ::: "memory");
        __syncthreads();

        // ---- accumulate: acc[r][*] += p[row_r][j] * Wh[j][cols] ----
        #pragma unroll 2
        for (int jc = 0; jc < TJ; jc += 4) {
            float4 pv0 = *(const float4*)&p_s[rg     ][jc];
            float4 pv1 = *(const float4*)&p_s[rg + 16][jc];
            float4 pv2 = *(const float4*)&p_s[rg + 32][jc];
            float4 pv3 = *(const float4*)&p_s[rg + 48][jc];
            const float* pa0 = (const float*)&pv0;
            const float* pa1 = (const float*)&pv1;
            const float* pa2 = (const float*)&pv2;
            const float* pa3 = (const float*)&pv3;
            #pragma unroll
            for (int jj = 0; jj < 4; jj++) {
                ulonglong2 wA = *(const ulonglong2*)&Wh_s[jc + jj][oA];
                ulonglong2 wB = *(const ulonglong2*)&Wh_s[jc + jj][oB];
                unsigned long long pd;
                pd = pack2(pa0[jj]);
                acc[0][0] = fma2(pd, wA.x, acc[0][0]);
                acc[0][1] = fma2(pd, wA.y, acc[0][1]);
                acc[0][2] = fma2(pd, wB.x, acc[0][2]);
                acc[0][3] = fma2(pd, wB.y, acc[0][3]);
                pd = pack2(pa1[jj]);
                acc[1][0] = fma2(pd, wA.x, acc[1][0]);
                acc[1][1] = fma2(pd, wA.y, acc[1][1]);
                acc[1][2] = fma2(pd, wB.x, acc[1][2]);
                acc[1][3] = fma2(pd, wB.y, acc[1][3]);
                pd = pack2(pa2[jj]);
                acc[2][0] = fma2(pd, wA.x, acc[2][0]);
                acc[2][1] = fma2(pd, wA.y, acc[2][1]);
                acc[2][2] = fma2(pd, wB.x, acc[2][2]);
                acc[2][3] = fma2(pd, wB.y, acc[2][3]);
                pd = pack2(pa3[jj]);
                acc[3][0] = fma2(pd, wA.x, acc[3][0]);
                acc[3][1] = fma2(pd, wA.y, acc[3][1]);
                acc[3][2] = fma2(pd, wB.x, acc[3][2]);
                acc[3][3] = fma2(pd, wB.y, acc[3][3]);
            }
        }
    }
    __syncthreads();   // all rowsum contributions landed

    float* pa = g_pacc[js] + ((size_t)b * N_ + i0) * FOUT;
    #pragma unroll
    for (int r = 0; r < 4; r++) {
        int row = rg + 16 * r;
        float2 v0 = *(float2*)&acc[r][0];
        float2 v1 = *(float2*)&acc[r][1];
        float2 v2 = *(float2*)&acc[r][2];
        float2 v3 = *(float2*)&acc[r][3];
        float4 oa = make_float4(v0.x, v0.y, v1.x, v1.y);
        float4 ob = make_float4(v2.x, v2.y, v3.x, v3.y);
        *(float4*)&pa[(size_t)row * FOUT + 8 * cg]     = oa;
        *(float4*)&pa[(size_t)row * FOUT + 8 * cg + 4] = ob;
    }
    if (tid < TI) g_psum[js][b * N_ + i0 + tid] = rowsum[tid];
}

// ---------------------------------------------------------------------------
// Kernel 3: combine partials: out = (sum_js pacc) / (sum_js psum)
// ---------------------------------------------------------------------------
__global__ void __launch_bounds__(256) k_comb(float* __restrict__ out) {
    int idx = blockIdx.x * 256 + threadIdx.x;      // float4 index
    int row = idx >> 4;                            // 16 float4 per row
    float4 s = *(const float4*)&g_pacc[0][(size_t)idx * 4];
    float den = g_psum[0][row];
    #pragma unroll
    for (int js = 1; js < JSPLIT; js++) {
        float4 c = *(const float4*)&g_pacc[js][(size_t)idx * 4];
        s.x += c.x; s.y += c.y; s.z += c.z; s.w += c.w;
        den += g_psum[js][row];
    }
    float inv = 1.0f / den;
    float4 o = make_float4(s.x * inv, s.y * inv, s.z * inv, s.w * inv);
    *(float4*)&out[(size_t)idx * 4] = o;
}

// ---------------------------------------------------------------------------
extern "C" void kernel_launch(void* const* d_in, const int* in_sizes, int n_in,
                              void* d_out, int out_size) {
    const float* h   = (const float*)d_in[0];
    const float* adj = (const float*)d_in[1];
    const float* W   = (const float*)d_in[2];
    const float* a   = (const float*)d_in[3];
    float* out = (float*)d_out;

    k_wh<<<(B_ * N_) / 64, 256>>>(h, W, a);

    dim3 grid(N_ / TI, JSPLIT, B_);
    k_attn<<<grid, TH>>>(adj);

    k_comb<<<(B_ * N_ * FOUT / 4) / 256, 256>>>(out);
}

// round 12
// speedup vs baseline: 1.7228x; 1.4818x over previous
#include <cuda_runtime.h>
#include <cuda_bf16.h>

#define B_     8
#define N_     2048
#define FIN    128
#define FOUT   64
#define ALPHA  0.2f
#define JSPLIT 4

// Scratch (device globals — no allocation allowed)
__device__ float g_Wh[B_ * N_ * FOUT];            // 4 MB (tf32-rounded values)
__device__ float g_f[B_ * N_];
__device__ float g_g[B_ * N_];
__device__ float g_pacc[JSPLIT][B_ * N_ * FOUT];  // 16 MB partial accumulators
__device__ float g_psum[JSPLIT][B_ * N_];         // partial rowsums

// ---------------------------------------------------------------------------
// helpers
// ---------------------------------------------------------------------------
__device__ __forceinline__ unsigned f2tf32(float x) {
    unsigned u;
    asm("cvt.rna.tf32.f32 %0, %1;" : "=r"(u) : "f"(x));
    return u;
}
// D(16x8) += A(16x8,tf32) * B(8x8,tf32), fp32 accumulate
__device__ __forceinline__ void mma_tf32(float* c,
                                         unsigned a0, unsigned a1,
                                         unsigned a2, unsigned a3,
                                         unsigned b0, unsigned b1) {
    asm("mma.sync.aligned.m16n8k8.row.col.f32.tf32.tf32.f32 "
        "{%0,%1,%2,%3}, {%4,%5,%6,%7}, {%8,%9}, {%0,%1,%2,%3};"
        : "+f"(c[0]), "+f"(c[1]), "+f"(c[2]), "+f"(c[3])
        : "r"(a0), "r"(a1), "r"(a2), "r"(a3), "r"(b0), "r"(b1));
}
__device__ __forceinline__ unsigned smem_u32(const void* p) {
    return (unsigned)__cvta_generic_to_shared(p);
}
#define CP16(dst, src) \
    asm volatile("cp.async.cg.shared.global [%0], [%1], 16;" :: "r"(dst), "l"(src))

// ---------------------------------------------------------------------------
// Kernel 1: Wh = h @ W ; f = Wh @ a1 ; g = Wh @ a2
// (round-10 version, 14us). Wh is stored TF32-ROUNDED (consumed by tensor-core
// mma in k_attn); f/g are reduced from the exact fp32 accumulators.
// ---------------------------------------------------------------------------
__global__ void __launch_bounds__(256) k_wh(const float* __restrict__ h,
                                            const float* __restrict__ W,
                                            const float* __restrict__ a) {
    __shared__ __align__(16) float W_s[FIN][FOUT];   // 32 KB
    __shared__ __align__(16) float h_s[64][132];     // 33.8 KB, padded

    int row0 = blockIdx.x * 64;
    int tid  = threadIdx.x;
    int fc4  = (tid & 15) * 4;        // 4 output cols
    int rg   = tid >> 4;              // 0..15 -> rows rg*4 .. rg*4+3

    #pragma unroll
    for (int l = 0; l < 8; l++) {
        int idx = tid + l * 256;
        *(float4*)&((float*)W_s)[idx * 4] = *(const float4*)&W[idx * 4];
    }
    #pragma unroll
    for (int l = 0; l < 8; l++) {
        int idx = tid + l * 256;
        int r = idx >> 5, q = idx & 31;
        *(float4*)&h_s[r][q * 4] =
            *(const float4*)&h[(size_t)(row0 + r) * FIN + q * 4];
    }
    __syncthreads();

    float acc[4][4];
    #pragma unroll
    for (int r = 0; r < 4; r++)
        #pragma unroll
        for (int c = 0; c < 4; c++) acc[r][c] = 0.f;

    #pragma unroll 2
    for (int k4 = 0; k4 < FIN; k4 += 4) {
        float4 w0 = *(const float4*)&W_s[k4 + 0][fc4];
        float4 w1 = *(const float4*)&W_s[k4 + 1][fc4];
        float4 w2 = *(const float4*)&W_s[k4 + 2][fc4];
        float4 w3 = *(const float4*)&W_s[k4 + 3][fc4];
        #pragma unroll
        for (int r = 0; r < 4; r++) {
            float4 hv = *(const float4*)&h_s[rg * 4 + r][k4];
            const float* wp0 = (const float*)&w0;
            const float* wp1 = (const float*)&w1;
            const float* wp2 = (const float*)&w2;
            const float* wp3 = (const float*)&w3;
            #pragma unroll
            for (int c = 0; c < 4; c++) {
                float t = acc[r][c];
                t = fmaf(hv.x, wp0[c], t);
                t = fmaf(hv.y, wp1[c], t);
                t = fmaf(hv.z, wp2[c], t);
                t = fmaf(hv.w, wp3[c], t);
                acc[r][c] = t;
            }
        }
    }

    float a1[4], a2[4];
    #pragma unroll
    for (int c = 0; c < 4; c++) { a1[c] = a[fc4 + c]; a2[c] = a[FOUT + fc4 + c]; }

    #pragma unroll
    for (int r = 0; r < 4; r++) {
        int row = row0 + rg * 4 + r;
        // tf32-rounded Wh for the tensor-core consumer
        float4 st;
        st.x = __uint_as_float(f2tf32(acc[r][0]));
        st.y = __uint_as_float(f2tf32(acc[r][1]));
        st.z = __uint_as_float(f2tf32(acc[r][2]));
        st.w = __uint_as_float(f2tf32(acc[r][3]));
        *(float4*)&g_Wh[(size_t)row * FOUT + fc4] = st;
        // f/g from exact fp32
        float pf = acc[r][0] * a1[0] + acc[r][1] * a1[1]
                 + acc[r][2] * a1[2] + acc[r][3] * a1[3];
        float pg = acc[r][0] * a2[0] + acc[r][1] * a2[1]
                 + acc[r][2] * a2[2] + acc[r][3] * a2[3];
        #pragma unroll
        for (int off = 1; off < 16; off <<= 1) {
            pf += __shfl_xor_sync(0xffffffffu, pf, off);
            pg += __shfl_xor_sync(0xffffffffu, pg, off);
        }
        if ((tid & 15) == 0) {
            g_f[row] = pf;
            g_g[row] = pg;
        }
    }
}

// ---------------------------------------------------------------------------
// Kernel 2: fused masked-softmax attention + tensor-core att@Wh.
// j-split into JSPLIT blocks; writes UNNORMALIZED partial acc + rowsums.
// 128 threads (4 warps), TI=64 rows, TJ=64 j-tile, 8 tiles/CTA.
//
// The score phase computes P directly in mma A-fragment layout (no shared
// round-trip): lane (g=lane>>2, tg=lane&3) of warp w owns
//   rows  r0=16w+g, r1=16w+g+8
//   cols  c = tg + 4t, t=0..15   (i.e. cols ≡ tg mod 4)
// which is exactly the m16n8k8 A layout for k-steps ks: a0=p0[2ks],
// a1=p1[2ks], a2=p0[2ks+1], a3=p1[2ks+1].
// Wh tile in shared, stride 72 -> B-frag LDS banks = 8*tg+g (conflict-free).
// Accumulators: 8 n-blocks x 4 fp32 regs, held across all 8 j-tiles.
// ---------------------------------------------------------------------------
#define TI 64
#define TJ 64
#define TH 128
#define STR 72

__global__ void __launch_bounds__(TH, 4) k_attn(const float* __restrict__ adj) {
    __shared__ __align__(16) float Wh_s[TJ][STR];   // 18.4 KB

    int i0    = blockIdx.x * TI;
    int js    = blockIdx.y;
    int b     = blockIdx.z;
    int jbase = js * (N_ / JSPLIT);
    int tid   = threadIdx.x;
    int w     = tid >> 5;
    int lane  = tid & 31;
    int g     = lane >> 2;
    int tg    = lane & 3;

    int r0 = 16 * w + g;          // tile-local rows
    int r1 = r0 + 8;

    const float* Wh_b = g_Wh + (size_t)b * N_ * FOUT;
    const float* ggp  = g_g + b * N_ + jbase;
    const float* adj0 = adj + (size_t)(i0 + r0) * N_ + jbase;
    const float* adj1 = adj + (size_t)(i0 + r1) * N_ + jbase;

    const float fi0 = g_f[b * N_ + i0 + r0];
    const float fi1 = g_f[b * N_ + i0 + r1];

    float acc[8][4];
    #pragma unroll
    for (int nb = 0; nb < 8; nb++)
        #pragma unroll
        for (int c = 0; c < 4; c++) acc[nb][c] = 0.f;

    float rs0 = 0.f, rs1 = 0.f;   // rowsum accumulators (valid after reduce)
    float p0[16], p1[16];

    for (int jt = 0; jt < (N_ / JSPLIT) / TJ; jt++) {
        int j0 = jt * TJ;              // offset within this j-split chunk
        if (jt) __syncthreads();       // prev mma done with Wh_s

        // ---- async-copy Wh tile gmem->shared, overlaps score phase ----
        #pragma unroll
        for (int l = 0; l < 8; l++) {
            int idx = tid + TH * l;            // 0..1023 16B chunks
            int row = idx >> 4, q = idx & 15;
            CP16(smem_u32(&Wh_s[row][q * 4]),
                 &Wh_b[(size_t)(jbase + j0 + row) * FOUT + q * 4]);
        }

        // ---- scores straight into A-fragment registers ----
        float s0 = 0.f, s1 = 0.f;
        #pragma unroll
        for (int t = 0; t < 16; t++) {
            int c = tg + 4 * t;
            float ad0 = adj0[j0 + c];
            float ad1 = adj1[j0 + c];
            float gv  = ggp[j0 + c];
            float v0 = fi0 + gv; v0 = fmaxf(v0, ALPHA * v0);
            float v1 = fi1 + gv; v1 = fmaxf(v1, ALPHA * v1);
            float q0 = (ad0 > 0.f) ? __expf(v0) : 0.f;
            float q1 = (ad1 > 0.f) ? __expf(v1) : 0.f;
            p0[t] = q0; p1[t] = q1;
            s0 += q0; s1 += q1;
        }
        s0 += __shfl_xor_sync(0xffffffffu, s0, 1);
        s0 += __shfl_xor_sync(0xffffffffu, s0, 2);
        s1 += __shfl_xor_sync(0xffffffffu, s1, 1);
        s1 += __shfl_xor_sync(0xffffffffu, s1, 2);
        rs0 += s0; rs1 += s1;

        asm volatile("cp.async.wait_all;" ::: "memory");
        __syncthreads();

        // ---- tensor-core accumulate: acc += P(16x64) @ Wh(64x64) ----
        #pragma unroll
        for (int ks = 0; ks < 8; ks++) {
            unsigned a0 = f2tf32(p0[2 * ks]);
            unsigned a1 = f2tf32(p1[2 * ks]);
            unsigned a2 = f2tf32(p0[2 * ks + 1]);
            unsigned a3 = f2tf32(p1[2 * ks + 1]);
            #pragma unroll
            for (int nb = 0; nb < 8; nb++) {
                unsigned b0 = __float_as_uint(Wh_s[8 * ks + tg    ][8 * nb + g]);
                unsigned b1 = __float_as_uint(Wh_s[8 * ks + tg + 4][8 * nb + g]);
                mma_tf32(acc[nb], a0, a1, a2, a3, b0, b1);
            }
        }
    }

    // ---- epilogue: unnormalized partials + partial rowsums ----
    float* pa = g_pacc[js] + ((size_t)b * N_ + i0) * FOUT;
    #pragma unroll
    for (int nb = 0; nb < 8; nb++) {
        *(float2*)&pa[(size_t)r0 * FOUT + 8 * nb + 2 * tg] =
            make_float2(acc[nb][0], acc[nb][1]);
        *(float2*)&pa[(size_t)r1 * FOUT + 8 * nb + 2 * tg] =
            make_float2(acc[nb][2], acc[nb][3]);
    }
    if (tg == 0) {
        g_psum[js][b * N_ + i0 + r0] = rs0;
        g_psum[js][b * N_ + i0 + r1] = rs1;
    }
}

// ---------------------------------------------------------------------------
// Kernel 3: combine partials: out = (sum_js pacc) / (sum_js psum)
// ---------------------------------------------------------------------------
__global__ void __launch_bounds__(256) k_comb(float* __restrict__ out) {
    int idx = blockIdx.x * 256 + threadIdx.x;      // float4 index
    int row = idx >> 4;                            // 16 float4 per row
    float4 s = *(const float4*)&g_pacc[0][(size_t)idx * 4];
    float den = g_psum[0][row];
    #pragma unroll
    for (int js = 1; js < JSPLIT; js++) {
        float4 c = *(const float4*)&g_pacc[js][(size_t)idx * 4];
        s.x += c.x; s.y += c.y; s.z += c.z; s.w += c.w;
        den += g_psum[js][row];
    }
    float inv = 1.0f / den;
    float4 o = make_float4(s.x * inv, s.y * inv, s.z * inv, s.w * inv);
    *(float4*)&out[(size_t)idx * 4] = o;
}

// ---------------------------------------------------------------------------
extern "C" void kernel_launch(void* const* d_in, const int* in_sizes, int n_in,
                              void* d_out, int out_size) {
    const float* h   = (const float*)d_in[0];
    const float* adj = (const float*)d_in[1];
    const float* W   = (const float*)d_in[2];
    const float* a   = (const float*)d_in[3];
    float* out = (float*)d_out;

    k_wh<<<(B_ * N_) / 64, 256>>>(h, W, a);

    dim3 grid(N_ / TI, JSPLIT, B_);
    k_attn<<<grid, TH>>>(adj);

    k_comb<<<(B_ * N_ * FOUT / 4) / 256, 256>>>(out);
}

// round 13
// speedup vs baseline: 1.7929x; 1.0407x over previous
#include <cuda_runtime.h>
#include <cuda_bf16.h>

#define B_     8
#define N_     2048
#define FIN    128
#define FOUT   64
#define ALPHA  0.2f
#define JSPLIT 4

// Scratch (device globals — no allocation allowed)
__device__ float    g_Wh[B_ * N_ * FOUT];            // 4 MB (tf32-rounded)
__device__ float    g_f[B_ * N_];
__device__ float    g_g[B_ * N_];
__device__ float    g_pacc[JSPLIT][B_ * N_ * FOUT];  // 16 MB partials
__device__ float    g_psum[JSPLIT][B_ * N_];
__device__ unsigned g_mask[N_ * N_ / 32];            // 512 KB packed adj

// ---------------------------------------------------------------------------
// helpers
// ---------------------------------------------------------------------------
__device__ __forceinline__ unsigned f2tf32(float x) {
    unsigned u;
    asm("cvt.rna.tf32.f32 %0, %1;" : "=r"(u) : "f"(x));
    return u;
}
// D(16x8) += A(16x8,tf32) * B(8x8,tf32), fp32 accumulate
__device__ __forceinline__ void mma_tf32(float* c,
                                         unsigned a0, unsigned a1,
                                         unsigned a2, unsigned a3,
                                         unsigned b0, unsigned b1) {
    asm("mma.sync.aligned.m16n8k8.row.col.f32.tf32.tf32.f32 "
        "{%0,%1,%2,%3}, {%4,%5,%6,%7}, {%8,%9}, {%0,%1,%2,%3};"
        : "+f"(c[0]), "+f"(c[1]), "+f"(c[2]), "+f"(c[3])
        : "r"(a0), "r"(a1), "r"(a2), "r"(a3), "r"(b0), "r"(b1));
}
__device__ __forceinline__ unsigned smem_u32(const void* p) {
    return (unsigned)__cvta_generic_to_shared(p);
}
#define CP16(dst, src) \
    asm volatile("cp.async.cg.shared.global [%0], [%1], 16;" :: "r"(dst), "l"(src))

// ---------------------------------------------------------------------------
// Kernel 0: pack adj>0 into bits. bit k of word w  <->  j = 32w + k.
// ---------------------------------------------------------------------------
__global__ void __launch_bounds__(256) k_pack(const float* __restrict__ adj) {
    int idx = blockIdx.x * 256 + threadIdx.x;        // element index in [0, N*N)
    float v = adj[idx];
    unsigned m = __ballot_sync(0xffffffffu, v > 0.f);
    if ((threadIdx.x & 31) == 0) g_mask[idx >> 5] = m;
}

// ---------------------------------------------------------------------------
// Kernel 1: Wh = h @ W ; f = Wh @ a1 ; g = Wh @ a2
// 32x64 tile (49 KB smem -> 3 CTAs/SM), 256 threads, 2 rows x 4 cols/thread.
// Wh stored TF32-ROUNDED; f/g from exact fp32 accumulators.
// ---------------------------------------------------------------------------
__global__ void __launch_bounds__(256) k_wh(const float* __restrict__ h,
                                            const float* __restrict__ W,
                                            const float* __restrict__ a) {
    __shared__ __align__(16) float W_s[FIN][FOUT];   // 32 KB
    __shared__ __align__(16) float h_s[32][132];     // 16.9 KB, padded

    int row0 = blockIdx.x * 32;
    int tid  = threadIdx.x;
    int fc4  = (tid & 15) * 4;        // 4 output cols
    int rg   = tid >> 4;              // 0..15 -> rows rg*2, rg*2+1

    #pragma unroll
    for (int l = 0; l < 8; l++) {
        int idx = tid + l * 256;
        *(float4*)&((float*)W_s)[idx * 4] = *(const float4*)&W[idx * 4];
    }
    #pragma unroll
    for (int l = 0; l < 4; l++) {
        int idx = tid + l * 256;          // 0..1023 float4
        int r = idx >> 5, q = idx & 31;
        *(float4*)&h_s[r][q * 4] =
            *(const float4*)&h[(size_t)(row0 + r) * FIN + q * 4];
    }
    __syncthreads();

    float acc[2][4];
    #pragma unroll
    for (int r = 0; r < 2; r++)
        #pragma unroll
        for (int c = 0; c < 4; c++) acc[r][c] = 0.f;

    #pragma unroll 2
    for (int k4 = 0; k4 < FIN; k4 += 4) {
        float4 w0 = *(const float4*)&W_s[k4 + 0][fc4];
        float4 w1 = *(const float4*)&W_s[k4 + 1][fc4];
        float4 w2 = *(const float4*)&W_s[k4 + 2][fc4];
        float4 w3 = *(const float4*)&W_s[k4 + 3][fc4];
        #pragma unroll
        for (int r = 0; r < 2; r++) {
            float4 hv = *(const float4*)&h_s[rg * 2 + r][k4];
            const float* wp0 = (const float*)&w0;
            const float* wp1 = (const float*)&w1;
            const float* wp2 = (const float*)&w2;
            const float* wp3 = (const float*)&w3;
            #pragma unroll
            for (int c = 0; c < 4; c++) {
                float t = acc[r][c];
                t = fmaf(hv.x, wp0[c], t);
                t = fmaf(hv.y, wp1[c], t);
                t = fmaf(hv.z, wp2[c], t);
                t = fmaf(hv.w, wp3[c], t);
                acc[r][c] = t;
            }
        }
    }

    float a1[4], a2[4];
    #pragma unroll
    for (int c = 0; c < 4; c++) { a1[c] = a[fc4 + c]; a2[c] = a[FOUT + fc4 + c]; }

    #pragma unroll
    for (int r = 0; r < 2; r++) {
        int row = row0 + rg * 2 + r;
        float4 st;
        st.x = __uint_as_float(f2tf32(acc[r][0]));
        st.y = __uint_as_float(f2tf32(acc[r][1]));
        st.z = __uint_as_float(f2tf32(acc[r][2]));
        st.w = __uint_as_float(f2tf32(acc[r][3]));
        *(float4*)&g_Wh[(size_t)row * FOUT + fc4] = st;
        float pf = acc[r][0] * a1[0] + acc[r][1] * a1[1]
                 + acc[r][2] * a1[2] + acc[r][3] * a1[3];
        float pg = acc[r][0] * a2[0] + acc[r][1] * a2[1]
                 + acc[r][2] * a2[2] + acc[r][3] * a2[3];
        #pragma unroll
        for (int off = 1; off < 16; off <<= 1) {
            pf += __shfl_xor_sync(0xffffffffu, pf, off);
            pg += __shfl_xor_sync(0xffffffffu, pg, off);
        }
        if ((tid & 15) == 0) {
            g_f[row] = pf;
            g_g[row] = pg;
        }
    }
}

// ---------------------------------------------------------------------------
// Kernel 2: fused masked-softmax attention + tensor-core att@Wh.
// Identical structure to round-12 (best), except adj is read from the packed
// bitmask: 2 x LDG.64 per row-tile instead of 32 scalar LDGs.
//   lane (g=lane>>2, tg=lane&3) of warp w owns rows {16w+g, 16w+g+8},
//   cols c = tg+4t (A-fragment layout); t<8 uses mask word .x, t>=8 .y.
// ---------------------------------------------------------------------------
#define TI 64
#define TJ 64
#define TH 128
#define STR 72

__global__ void __launch_bounds__(TH, 4) k_attn() {
    __shared__ __align__(16) float Wh_s[TJ][STR];   // 18.4 KB

    int i0    = blockIdx.x * TI;
    int js    = blockIdx.y;
    int b     = blockIdx.z;
    int jbase = js * (N_ / JSPLIT);
    int tid   = threadIdx.x;
    int w     = tid >> 5;
    int lane  = tid & 31;
    int g     = lane >> 2;
    int tg    = lane & 3;

    int r0 = 16 * w + g;          // tile-local rows
    int r1 = r0 + 8;

    const float*    Wh_b = g_Wh + (size_t)b * N_ * FOUT;
    const float*    ggp  = g_g + b * N_ + jbase;
    const unsigned* mk0  = g_mask + (size_t)(i0 + r0) * (N_ / 32) + (jbase >> 5);
    const unsigned* mk1  = g_mask + (size_t)(i0 + r1) * (N_ / 32) + (jbase >> 5);

    const float fi0 = g_f[b * N_ + i0 + r0];
    const float fi1 = g_f[b * N_ + i0 + r1];

    float acc[8][4];
    #pragma unroll
    for (int nb = 0; nb < 8; nb++)
        #pragma unroll
        for (int c = 0; c < 4; c++) acc[nb][c] = 0.f;

    float rs0 = 0.f, rs1 = 0.f;
    float p0[16], p1[16];

    for (int jt = 0; jt < (N_ / JSPLIT) / TJ; jt++) {
        int j0 = jt * TJ;              // offset within this j-split chunk
        if (jt) __syncthreads();       // prev mma done with Wh_s

        // ---- async-copy Wh tile gmem->shared, overlaps score phase ----
        #pragma unroll
        for (int l = 0; l < 8; l++) {
            int idx = tid + TH * l;            // 0..1023 16B chunks
            int row = idx >> 4, q = idx & 15;
            CP16(smem_u32(&Wh_s[row][q * 4]),
                 &Wh_b[(size_t)(jbase + j0 + row) * FOUT + q * 4]);
        }

        // ---- mask words for this tile (64 bits per row) ----
        uint2 mw0 = *(const uint2*)&mk0[j0 >> 5];
        uint2 mw1 = *(const uint2*)&mk1[j0 >> 5];

        // ---- scores straight into A-fragment registers ----
        float s0 = 0.f, s1 = 0.f;
        #pragma unroll
        for (int t = 0; t < 16; t++) {
            int c  = tg + 4 * t;
            int cb = c & 31;
            unsigned m0 = (t < 8) ? mw0.x : mw0.y;
            unsigned m1 = (t < 8) ? mw1.x : mw1.y;
            float gv = ggp[j0 + c];
            float v0 = fi0 + gv; v0 = fmaxf(v0, ALPHA * v0);
            float v1 = fi1 + gv; v1 = fmaxf(v1, ALPHA * v1);
            float q0 = ((m0 >> cb) & 1u) ? __expf(v0) : 0.f;
            float q1 = ((m1 >> cb) & 1u) ? __expf(v1) : 0.f;
            p0[t] = q0; p1[t] = q1;
            s0 += q0; s1 += q1;
        }
        s0 += __shfl_xor_sync(0xffffffffu, s0, 1);
        s0 += __shfl_xor_sync(0xffffffffu, s0, 2);
        s1 += __shfl_xor_sync(0xffffffffu, s1, 1);
        s1 += __shfl_xor_sync(0xffffffffu, s1, 2);
        rs0 += s0; rs1 += s1;

        asm volatile("cp.async.wait_all;" ::: "memory");
        __syncthreads();

        // ---- tensor-core accumulate: acc += P(16x64) @ Wh(64x64) ----
        #pragma unroll
        for (int ks = 0; ks < 8; ks++) {
            unsigned a0 = f2tf32(p0[2 * ks]);
            unsigned a1 = f2tf32(p1[2 * ks]);
            unsigned a2 = f2tf32(p0[2 * ks + 1]);
            unsigned a3 = f2tf32(p1[2 * ks + 1]);
            #pragma unroll
            for (int nb = 0; nb < 8; nb++) {
                unsigned b0 = __float_as_uint(Wh_s[8 * ks + tg    ][8 * nb + g]);
                unsigned b1 = __float_as_uint(Wh_s[8 * ks + tg + 4][8 * nb + g]);
                mma_tf32(acc[nb], a0, a1, a2, a3, b0, b1);
            }
        }
    }

    // ---- epilogue: unnormalized partials + partial rowsums ----
    float* pa = g_pacc[js] + ((size_t)b * N_ + i0) * FOUT;
    #pragma unroll
    for (int nb = 0; nb < 8; nb++) {
        *(float2*)&pa[(size_t)r0 * FOUT + 8 * nb + 2 * tg] =
            make_float2(acc[nb][0], acc[nb][1]);
        *(float2*)&pa[(size_t)r1 * FOUT + 8 * nb + 2 * tg] =
            make_float2(acc[nb][2], acc[nb][3]);
    }
    if (tg == 0) {
        g_psum[js][b * N_ + i0 + r0] = rs0;
        g_psum[js][b * N_ + i0 + r1] = rs1;
    }
}

// ---------------------------------------------------------------------------
// Kernel 3: combine partials: out = (sum_js pacc) / (sum_js psum)
// ---------------------------------------------------------------------------
__global__ void __launch_bounds__(256) k_comb(float* __restrict__ out) {
    int idx = blockIdx.x * 256 + threadIdx.x;      // float4 index
    int row = idx >> 4;                            // 16 float4 per row
    float4 s = *(const float4*)&g_pacc[0][(size_t)idx * 4];
    float den = g_psum[0][row];
    #pragma unroll
    for (int js = 1; js < JSPLIT; js++) {
        float4 c = *(const float4*)&g_pacc[js][(size_t)idx * 4];
        s.x += c.x; s.y += c.y; s.z += c.z; s.w += c.w;
        den += g_psum[js][row];
    }
    float inv = 1.0f / den;
    float4 o = make_float4(s.x * inv, s.y * inv, s.z * inv, s.w * inv);
    *(float4*)&out[(size_t)idx * 4] = o;
}

// ---------------------------------------------------------------------------
extern "C" void kernel_launch(void* const* d_in, const int* in_sizes, int n_in,
                              void* d_out, int out_size) {
    const float* h   = (const float*)d_in[0];
    const float* adj = (const float*)d_in[1];
    const float* W   = (const float*)d_in[2];
    const float* a   = (const float*)d_in[3];
    float* out = (float*)d_out;

    k_pack<<<(N_ * N_) / 256, 256>>>(adj);
    k_wh<<<(B_ * N_) / 32, 256>>>(h, W, a);

    dim3 grid(N_ / TI, JSPLIT, B_);
    k_attn<<<grid, TH>>>();

    k_comb<<<(B_ * N_ * FOUT / 4) / 256, 256>>>(out);
}